// round 9
// baseline (speedup 1.0000x reference)
#include <cuda_runtime.h>

// rho' = L rho L^T,  L = A (x) B (x) C  (flat = r*64 + c*4 + j; r,c in [0,16),
// j in [0,4)).  A,B identity outside 0..3 -> independent row classes:
//   D  : {r<4,c<4}   64 rows  -> blocks 0..15   (64 rows x 64 cols, smem)
//   Bc : {r>=4,c<4}  12 x 16  -> column-major register path
//   Cc : {r<4,c>=4}  12 x 16  -> column-major register path
//   Am : {r>=4,c>=4} 36 x 16  -> column-major register path
// 16-row blocks: thread owns ONE column (16 floats). Row-side mixing is fully
// in registers; column-side C (j-quads = 4 adjacent lanes) and B (c'<4 =
// warp-local lane group) are shuffles. chunk!=0 -> 0 syncs, 0 smem.
// chunk==0 adds one smem col-A stage (2 syncs). Matrices are built per-warp
// (each lane computes one of A/B/C; broadcast by shuffle) -> no barrier for
// the matrix build. Heavy blocks are ordered first to shrink the tail.

__device__ __forceinline__ void mix4s(float* p, const int st, const float* M)
{
    float v0 = p[0], v1 = p[st], v2 = p[2*st], v3 = p[3*st];
    p[0]    = M[0] *v0 + M[1] *v1 + M[2] *v2 + M[3] *v3;
    p[st]   = M[4] *v0 + M[5] *v1 + M[6] *v2 + M[7] *v3;
    p[2*st] = M[8] *v0 + M[9] *v1 + M[10]*v2 + M[11]*v3;
    p[3*st] = M[12]*v0 + M[13]*v1 + M[14]*v2 + M[15]*v3;
}

__device__ __forceinline__ void mix4r(float* v, const int st, const float* M)
{
    float v0 = v[0], v1 = v[st], v2 = v[2*st], v3 = v[3*st];
    v[0]    = M[0] *v0 + M[1] *v1 + M[2] *v2 + M[3] *v3;
    v[st]   = M[4] *v0 + M[5] *v1 + M[6] *v2 + M[7] *v3;
    v[2*st] = M[8] *v0 + M[9] *v1 + M[10]*v2 + M[11]*v3;
    v[3*st] = M[12]*v0 + M[13]*v1 + M[14]*v2 + M[15]*v3;
}

__device__ __forceinline__ float4 mixf4(float4 v, const float* M)
{
    float4 r;
    r.x = M[0] *v.x + M[1] *v.y + M[2] *v.z + M[3] *v.w;
    r.y = M[4] *v.x + M[5] *v.y + M[6] *v.z + M[7] *v.w;
    r.z = M[8] *v.x + M[9] *v.y + M[10]*v.z + M[11]*v.w;
    r.w = M[12]*v.x + M[13]*v.y + M[14]*v.z + M[15]*v.w;
    return r;
}

__device__ __forceinline__ void mixquad(float4* y, const float* M)
{
    float4 v0 = y[0], v1 = y[1], v2 = y[2], v3 = y[3];
#define MQ(c) \
    y[0].c = M[0] *v0.c + M[1] *v1.c + M[2] *v2.c + M[3] *v3.c; \
    y[1].c = M[4] *v0.c + M[5] *v1.c + M[6] *v2.c + M[7] *v3.c; \
    y[2].c = M[8] *v0.c + M[9] *v1.c + M[10]*v2.c + M[11]*v3.c; \
    y[3].c = M[12]*v0.c + M[13]*v1.c + M[14]*v2.c + M[15]*v3.c;
    MQ(x) MQ(y) MQ(z) MQ(w)
#undef MQ
}

// Per-warp matrix build: lane L computes the Givens product for (L % 3);
// lanes 0/1/2 hold A/B/C, broadcast via shuffles. No barriers. ALWAYS fills
// all three outputs (R8 fix: Bc chunk-0 blocks need A4 for the col-A stage).
__device__ __forceinline__ void build_mats(const float* __restrict__ thetas,
                                           int lane,
                                           float* A4, float* B4, float* C4)
{
    float M[16] = {1,0,0,0, 0,1,0,0, 0,0,1,0, 0,0,0,1};
    const int pi[6] = {0,0,0,1,1,2};
    const int pj[6] = {1,2,3,2,3,3};
    const int base = (lane % 3) * 6;
#pragma unroll
    for (int g = 0; g < 6; ++g) {
        float th = thetas[base + g];
        float sn, cs;
        __sincosf(th, &sn, &cs);
        int i = pi[g], j = pj[g];
#pragma unroll
        for (int k = 0; k < 4; ++k) {
            float ai = M[i*4 + k], aj = M[j*4 + k];
            M[i*4 + k] =  cs * ai + sn * aj;   // M <- G * M
            M[j*4 + k] = -sn * ai + cs * aj;
        }
    }
#pragma unroll
    for (int k = 0; k < 16; ++k) {
        A4[k] = __shfl_sync(0xffffffffu, M[k], 0);
        B4[k] = __shfl_sync(0xffffffffu, M[k], 1);
        C4[k] = __shfl_sync(0xffffffffu, M[k], 2);
    }
}

// Column-side C and B mixes on a register column v[16]; t = column in [0,256).
__device__ __forceinline__ void colmix_CB(float* v, int t,
                                          const float* B4, const float* C4)
{
    const unsigned F = 0xffffffffu;
    const int lane = t & 31;
    const int j  = lane & 3;
    const int bj = lane & ~3;
    // col C: out_j = sum_k C[j,k] * val(lane bj+k)
    float c0 = C4[j*4+0], c1 = C4[j*4+1], c2 = C4[j*4+2], c3 = C4[j*4+3];
#pragma unroll
    for (int l = 0; l < 16; ++l) {
        float x  = v[l];
        float s0 = __shfl_sync(F, x, bj + 0);
        float s1 = __shfl_sync(F, x, bj + 1);
        float s2 = __shfl_sync(F, x, bj + 2);
        float s3 = __shfl_sync(F, x, bj + 3);
        v[l] = c0*s0 + c1*s1 + c2*s2 + c3*s3;
    }
    // col B: c'<4 lives in the low warp of each 64-col group (warp-uniform).
    if ((t & 32) == 0) {
        const int  cg  = (t >> 2) & 15;       // c' in 0..7 here
        const bool doB = (cg < 4);
        const int  ci  = doB ? cg : 0;
        float b0 = B4[ci*4+0], b1 = B4[ci*4+1], b2 = B4[ci*4+2], b3 = B4[ci*4+3];
#pragma unroll
        for (int l = 0; l < 16; ++l) {
            float x  = v[l];
            float s0 = __shfl_sync(F, x, j + 0);
            float s1 = __shfl_sync(F, x, j + 4);
            float s2 = __shfl_sync(F, x, j + 8);
            float s3 = __shfl_sync(F, x, j + 12);
            float nv = b0*s0 + b1*s1 + b2*s2 + b3*s3;
            if (doB) v[l] = nv;
        }
    }
}

// class decode for 16-row blocks: cls in [0,60)
__device__ __forceinline__ int class_row(int cls, int l)
{
    if (cls < 12)  return (4 + cls) * 64 + l;                           // Bc
    if (cls < 24)  return (l >> 2) * 64 + (4 + cls - 12) * 4 + (l & 3); // Cc
    int g = cls - 24;                                                   // Am
    return (4 + g / 3) * 64 + (4 + (g % 3) * 4) * 4 + l;
}

__global__ __launch_bounds__(256)
void rbs_fused(const float* __restrict__ in, float* __restrict__ out,
               const float* __restrict__ thetas)
{
    __shared__ float s[5120];   // D: 64x80 ; chunk-0 generic: 16x320

    const int t = threadIdx.x;
    const int b = blockIdx.x;
    const int lane = t & 31;

    const float4* in4  = reinterpret_cast<const float4*>(in);
    float4*       out4 = reinterpret_cast<float4*>(out);

    if (b >= 16) {
        // ========== 16-ROW CLASSES, column-major register path =============
        int cls, chunk;
        if (b < 76) { cls = b - 16;       chunk = 0; }            // heavy first
        else        { int id = b - 76; cls = id / 3; chunk = 1 + (id % 3); }
        const int typ  = (cls < 12) ? 0 : (cls < 24) ? 1 : 2;
        const int gcol = chunk * 256 + t;

        // load own column (16 coalesced 32-bit loads)
        float v[16];
#pragma unroll
        for (int l = 0; l < 16; ++l)
            v[l] = in[(size_t)class_row(cls, l) * 1024 + gcol];

        // matrices (per-warp, no barrier)
        float A4[16], B4[16], C4[16];
        build_mats(thetas, lane, A4, B4, C4);

        // row-side mixing fully in registers
#pragma unroll
        for (int q = 0; q < 4; ++q) mix4r(&v[q*4], 1, C4);        // row C (j)
        if (typ == 0) {
#pragma unroll
            for (int j2 = 0; j2 < 4; ++j2) mix4r(&v[j2], 4, B4);  // row B (c)
        } else if (typ == 1) {
#pragma unroll
            for (int j2 = 0; j2 < 4; ++j2) mix4r(&v[j2], 4, A4);  // row A (r)
        }

        // col A (rc'<4 = global cols 0..255): chunk-0 blocks only, via smem
        if (chunk == 0) {
            const int pc = t + 4 * (t >> 4);
#pragma unroll
            for (int l = 0; l < 16; ++l) s[l*320 + pc] = v[l];
            __syncthreads();
#pragma unroll
            for (int h = 0; h < 4; ++h) {
                int g2 = t + 256*h;
                int l2 = g2 >> 6, q = g2 & 63;
                mix4s(&s[l2*320 + q + 4*(q >> 4)], 80, A4);
            }
            __syncthreads();
#pragma unroll
            for (int l = 0; l < 16; ++l) v[l] = s[l*320 + pc];
        }

        // col C + col B in registers via warp shuffles, then store
        colmix_CB(v, t, B4, C4);
#pragma unroll
        for (int l = 0; l < 16; ++l)
            out[(size_t)class_row(cls, l) * 1024 + gcol] = v[l];

    } else {
        // ========== TYPE D: 64 rows {r<4,c<4} x 64 cols (blocks 0..15) =====
        const int ccq = b & 3, chunk = b >> 2;
        const int l = t >> 2, rcl = t & 3;          // slot: row l, rc'-strip
        const int grow = (l >> 4)*64 + (l & 15);
        const int gb = (chunk*4 + rcl)*16 + ccq*4;  // float4 base in row

        // load raw -> smem (row stride 80, pad 4 per 16)
        {
            float4 x[4];
#pragma unroll
            for (int w = 0; w < 4; ++w) x[w] = in4[grow*256 + gb + w];
#pragma unroll
            for (int w = 0; w < 4; ++w)
                *reinterpret_cast<float4*>(&s[l*80 + rcl*20 + w*4]) = x[w];
        }
        float A4[16], B4[16], C4[16];
        build_mats(thetas, lane, A4, B4, C4);
        __syncthreads();

        // row C (j) + row B (cc) in registers: thread owns (rr, col)
        {
            const int rr = t >> 6, q = t & 63;
            const int pc = q + 4*(q >> 4);
            float v[16];
#pragma unroll
            for (int k = 0; k < 16; ++k) v[k] = s[(rr*16 + k)*80 + pc];
#pragma unroll
            for (int cc = 0; cc < 4; ++cc) mix4r(&v[cc*4], 1, C4);
#pragma unroll
            for (int j = 0; j < 4; ++j)    mix4r(&v[j], 4, B4);
#pragma unroll
            for (int k = 0; k < 16; ++k) s[(rr*16 + k)*80 + pc] = v[k];
        }
        __syncthreads();

        // row A across rr (stride 16 rows)
#pragma unroll
        for (int h = 0; h < 4; ++h) {
            int g2 = t + 256*h;
            int ccj = g2 >> 6, q = g2 & 63;
            mix4s(&s[ccj*80 + q + 4*(q >> 4)], 16*80, A4);
        }
        __syncthreads();

        // col A (across rcl strips): chunk 0 only
        if (chunk == 0) {
#pragma unroll
            for (int h = 0; h < 4; ++h) {
                int g2 = t + 256*h;
                int l2 = g2 >> 4, wj = g2 & 15;
                mix4s(&s[l2*80 + wj], 20, A4);
            }
            __syncthreads();
        }

        // store: col B (ccq==0) + col C in registers
        {
            float4 y[4];
#pragma unroll
            for (int w = 0; w < 4; ++w)
                y[w] = *reinterpret_cast<float4*>(&s[l*80 + rcl*20 + w*4]);
            if (ccq == 0) mixquad(y, B4);
#pragma unroll
            for (int w = 0; w < 4; ++w)
                out4[grow*256 + gb + w] = mixf4(y[w], C4);
        }
    }
}

extern "C" void kernel_launch(void* const* d_in, const int* in_sizes, int n_in,
                              void* d_out, int out_size)
{
    const float* state  = nullptr;
    const float* thetas = nullptr;
    for (int i = 0; i < n_in; ++i) {
        if (in_sizes[i] == 18 && !thetas)
            thetas = (const float*)d_in[i];
        else if (in_sizes[i] == 1024 * 1024 && !state)
            state = (const float*)d_in[i];
    }
    rbs_fused<<<256, 256>>>(state, (float*)d_out, thetas);
}